// round 12
// baseline (speedup 1.0000x reference)
#include <cuda_runtime.h>
#include <cuda_fp16.h>
#include <cstdint>
#include <math.h>

// ---------------- problem constants ----------------
#define B_      64
#define V_      49
#define NPATCH  196
#define CIN     12
#define PSZ     16
#define IMG     224
#define ENC     768
#define DEC     512
#define NL      8
#define NH      16
#define HD      32
#define FFN     2048
#define OUTD    3072
#define ROWS_V  (B_ * V_)       // 3136
#define ROWS_N  (B_ * NPATCH)   // 12544

// ---------------- scratch ----------------
__device__ __half g_patchh[ROWS_V * OUTD];
__device__ __half g_ench  [ROWS_V * ENC];
__device__ float  g_dec   [ROWS_V * DEC];
__device__ float  g_h     [ROWS_N * DEC];
__device__ __half g_hh    [ROWS_N * DEC];
__device__ float  g_tmp   [ROWS_N * DEC];
__device__ __half g_attnh [ROWS_N * DEC];
__device__ __half g_qkvh  [ROWS_N * 3 * DEC];
__device__ __half g_ffnh  [ROWS_N * FFN];
__device__ __half g_wh    [29491200];        // fp16 weights, TRANSPOSED to [N,K]
__device__ int    g_visidx[B_ * V_];
__device__ int    g_src   [B_ * NPATCH];

// weight-scratch offsets (halfs)
#define WT_WP   0
#define WT_E2D  2359296
#define WT_QKV  2752512
#define WT_O    9043968
#define WT_W1   11141120
#define WT_W2   19529728
#define WT_R    27918336

// ---------------- helpers ----------------
__device__ __forceinline__ float gelu_exact(float v) {
    return 0.5f * v * (1.0f + erff(v * 0.7071067811865476f));
}
__device__ __forceinline__ void cp_async16(void* smem_dst, const void* gmem_src, bool pred) {
    uint32_t saddr = (uint32_t)__cvta_generic_to_shared(smem_dst);
    int sz = pred ? 16 : 0;
    asm volatile("cp.async.cg.shared.global [%0], [%1], 16, %2;\n"
                 :: "r"(saddr), "l"(gmem_src), "r"(sz));
}
__device__ __forceinline__ void mma_f16(float* c, const uint32_t* a, const uint32_t* b) {
    asm volatile(
        "mma.sync.aligned.m16n8k16.row.col.f32.f16.f16.f32 "
        "{%0,%1,%2,%3}, {%4,%5,%6,%7}, {%8,%9}, {%0,%1,%2,%3};"
        : "+f"(c[0]), "+f"(c[1]), "+f"(c[2]), "+f"(c[3])
        : "r"(a[0]), "r"(a[1]), "r"(a[2]), "r"(a[3]), "r"(b[0]), "r"(b[1]));
}
__device__ __forceinline__ void ldsm4(uint32_t* r, uint32_t saddr) {
    asm volatile("ldmatrix.sync.aligned.m8n8.x4.shared.b16 {%0,%1,%2,%3}, [%4];"
                 : "=r"(r[0]), "=r"(r[1]), "=r"(r[2]), "=r"(r[3]) : "r"(saddr));
}

// ---------------- fused weight prep: all transposes in one kernel ----------------
// 32x32 tiles; block (32,8). Tile ranges per matrix (total 28800).
__global__ void fused_tr(const float* __restrict__ Wp, const float* __restrict__ We2d,
                         const float* __restrict__ Wqkv, const float* __restrict__ Wo,
                         const float* __restrict__ W1, const float* __restrict__ W2,
                         const float* __restrict__ Wr, __half* __restrict__ wh) {
    __shared__ float t[32][33];
    int tile = blockIdx.x;
    const float* src; __half* dst; int K, N;
    if (tile < 2304)        { src = Wp;   dst = wh + WT_WP;  K = OUTD; N = ENC; }
    else if (tile < 2688)   { tile -= 2304; src = We2d; dst = wh + WT_E2D; K = ENC; N = DEC; }
    else if (tile < 8832)   { tile -= 2688; int l = tile / 768;  tile -= l * 768;
                              src = Wqkv + (size_t)l * DEC * 3 * DEC;
                              dst = wh + WT_QKV + (size_t)l * 3 * DEC * DEC; K = DEC; N = 3 * DEC; }
    else if (tile < 10880)  { tile -= 8832; int l = tile / 256;  tile -= l * 256;
                              src = Wo + (size_t)l * DEC * DEC;
                              dst = wh + WT_O + (size_t)l * DEC * DEC; K = DEC; N = DEC; }
    else if (tile < 19072)  { tile -= 10880; int l = tile / 1024; tile -= l * 1024;
                              src = W1 + (size_t)l * DEC * FFN;
                              dst = wh + WT_W1 + (size_t)l * DEC * FFN; K = DEC; N = FFN; }
    else if (tile < 27264)  { tile -= 19072; int l = tile / 1024; tile -= l * 1024;
                              src = W2 + (size_t)l * FFN * DEC;
                              dst = wh + WT_W2 + (size_t)l * FFN * DEC; K = FFN; N = DEC; }
    else                    { tile -= 27264; src = Wr; dst = wh + WT_R; K = DEC; N = OUTD; }
    int ntx = N / 32;
    int kb = (tile / ntx) * 32, nb = (tile % ntx) * 32;
    #pragma unroll
    for (int i = 0; i < 4; i++)
        t[threadIdx.y + 8 * i][threadIdx.x] =
            src[(size_t)(kb + threadIdx.y + 8 * i) * N + nb + threadIdx.x];
    __syncthreads();
    #pragma unroll
    for (int i = 0; i < 4; i++)
        dst[(size_t)(nb + threadIdx.y + 8 * i) * K + kb + threadIdx.x] =
            __float2half_rn(t[threadIdx.x][threadIdx.y + 8 * i]);
}

// ---------------- mask scan ----------------
__global__ void scan_kernel(const int* __restrict__ mask) {
    int b = threadIdx.x;
    if (b >= B_) return;
    int cnt = 0;
    for (int n = 0; n < NPATCH; n++) {
        int m = mask[b * NPATCH + n];
        if (m == 0) {
            if (cnt < V_) g_visidx[b * V_ + cnt] = n;
            g_src[b * NPATCH + n] = (cnt < V_) ? cnt : (V_ - 1);
            cnt++;
        } else {
            g_src[b * NPATCH + n] = -1;
        }
    }
    for (int c = cnt; c < V_; c++) g_visidx[b * V_ + c] = 0;
}

// ---------------- patchify -> fp16 ----------------
__global__ void patchify_kernel(const float* __restrict__ x) {
    int r  = blockIdx.x;
    int b  = r / V_;
    int n  = g_visidx[r];
    int hp = n / (IMG / PSZ);
    int wp = n % (IMG / PSZ);
    for (int f = threadIdx.x; f < OUTD; f += blockDim.x) {
        int c  = f >> 8;
        int ph = (f >> 4) & 15;
        int pw = f & 15;
        float v = x[((b * CIN + c) * IMG + hp * PSZ + ph) * IMG + wp * PSZ + pw];
        g_patchh[(size_t)r * OUTD + f] = __float2half_rn(v);
    }
}

// ---------------- assemble ----------------
__global__ void assemble_kernel(const float* __restrict__ mask_token,
                                const float* __restrict__ pos_embed) {
    int row = blockIdx.x;
    int b = row / NPATCH;
    int n = row % NPATCH;
    int s = g_src[row];
    const float4* src = (s >= 0)
        ? (const float4*)&g_dec[(b * V_ + s) * DEC]
        : (const float4*)mask_token;
    const float4* pos = (const float4*)&pos_embed[n * DEC];
    int t = threadIdx.x;
    float4 a = src[t], p = pos[t];
    float4 v = make_float4(a.x + p.x, a.y + p.y, a.z + p.z, a.w + p.w);
    ((float4*)&g_h[(size_t)row * DEC])[t] = v;
    __half2* hh = (__half2*)&g_hh[(size_t)row * DEC];
    hh[t * 2 + 0] = __floats2half2_rn(v.x, v.y);
    hh[t * 2 + 1] = __floats2half2_rn(v.z, v.w);
}

// ---------------- fp16 tensor-core GEMM: 512 threads, 16 warps, 32x32 warp tile ----
#define BM 128
#define BN 128
#define BK 32
#define STRH 40                          // halfs per smem row (32 + pad 8) = 80 B
#define TILEH (128 * STRH)               // 5120 halfs per tile
#define STAGEH (2 * TILEH)               // A + B
#define NSTAGE 3
#define GEMM_SMEM (NSTAGE * STAGEH * 2)  // 61440 B
#define FLAG_GELU 1

__device__ __forceinline__ void gemm_load_stage(
    const __half* __restrict__ A, const __half* __restrict__ Wt,
    __half* sm, int s, int c, int bm, int bn, int M, int K, int t)
{
    __half* base = sm + s * STAGEH;
    int k0 = c * BK;
    #pragma unroll
    for (int i = 0; i < 2; i++) {
        int idx = t + (i << 9);              // 0..1023 (16B = 8 halfs each)
        int part = idx >> 9;                 // 0 = A, 1 = B
        int sub  = idx & 511;
        int row  = sub >> 2;                 // 0..127
        int c8   = sub & 3;                  // 0..3
        const __half* src;
        int ok = 1;
        if (part == 0) {
            int gr = bm + row;
            if (gr >= M) { ok = 0; gr = M - 1; }
            src = A + (size_t)gr * K + k0 + c8 * 8;
        } else {
            src = Wt + (size_t)(bn + row) * K + k0 + c8 * 8;
        }
        cp_async16(base + part * TILEH + row * STRH + c8 * 8, src, ok);
    }
    asm volatile("cp.async.commit_group;\n");
}

__global__ __launch_bounds__(512, 2) void gemm_tc_kernel(
    const __half* __restrict__ A, const __half* __restrict__ Wt,
    const float* __restrict__ bias, const float* __restrict__ resid,
    float* __restrict__ C, __half* __restrict__ Ch,
    int M, int N, int K, int flags)
{
    extern __shared__ __half sm[];

    const int t = threadIdx.x;
    const int bn = blockIdx.x * BN;
    const int bm = blockIdx.y * BM;
    const int warp = t >> 5, lane = t & 31;
    const int wm = warp >> 2, wn = warp & 3;     // 4 x 4 warps, warp tile 32x32
    const int lq = lane >> 2, lr = lane & 3;
    const int g  = lane >> 3;                    // ldmatrix group 0..3
    const int gr = lane & 7;

    float acc[2][4][4] = {};

    const int nch = K / BK;
    gemm_load_stage(A, Wt, sm, 0, 0, bm, bn, M, K, t);
    if (nch > 1) gemm_load_stage(A, Wt, sm, 1, 1, bm, bn, M, K, t);

    // ldmatrix per-thread base offsets (halfs)
    const int a_off = (wm * 32 + (g & 1) * 8 + gr) * STRH + (g >> 1) * 8;
    const int b_off = (wn * 32 + g * 8 + gr) * STRH;

    for (int c = 0; c < nch; c++) {
        int s = c - (c / NSTAGE) * NSTAGE;
        if (c + 1 < nch) asm volatile("cp.async.wait_group 1;\n");
        else             asm volatile("cp.async.wait_group 0;\n");
        __syncthreads();
        if (c + 2 < nch) {
            int s2 = (c + 2) - ((c + 2) / NSTAGE) * NSTAGE;
            gemm_load_stage(A, Wt, sm, s2, c + 2, bm, bn, M, K, t);
        }

        const __half* Ab = sm + s * STAGEH;
        const __half* Bb = Ab + TILEH;
        uint32_t a_base = (uint32_t)__cvta_generic_to_shared(Ab + a_off);
        uint32_t b_base = (uint32_t)__cvta_generic_to_shared(Bb + b_off);

        #pragma unroll
        for (int ks = 0; ks < 2; ks++) {          // two k16 steps per BK=32 chunk
            const int kh = ks * 16;
            uint32_t af[2][4];
            uint32_t b0[4], b1[4];
            #pragma unroll
            for (int mi = 0; mi < 2; mi++)
                ldsm4(af[mi], a_base + (mi * 16 * STRH + kh) * 2);
            ldsm4(b0, b_base + (kh + 0) * 2);
            ldsm4(b1, b_base + (kh + 8) * 2);
            #pragma unroll
            for (int mi = 0; mi < 2; mi++)
                #pragma unroll
                for (int ni = 0; ni < 4; ni++) {
                    uint32_t bf[2] = { b0[ni], b1[ni] };
                    mma_f16(acc[mi][ni], af[mi], bf);
                }
        }
        __syncthreads();
    }

    const bool dogelu = (flags & FLAG_GELU) != 0;

    #pragma unroll
    for (int mi = 0; mi < 2; mi++) {
        int r0 = bm + wm * 32 + mi * 16 + lq;
        #pragma unroll
        for (int ni = 0; ni < 4; ni++) {
            int col = bn + wn * 32 + ni * 8 + lr * 2;
            float bx = bias[col], by = bias[col + 1];
            float* a4 = acc[mi][ni];
            #pragma unroll
            for (int half = 0; half < 2; half++) {
                int r = r0 + half * 8;
                if (r >= M) continue;
                float vx = a4[half * 2 + 0] + bx;
                float vy = a4[half * 2 + 1] + by;
                if (resid) {
                    const float* rr = resid + (size_t)r * N + col;
                    vx += rr[0]; vy += rr[1];
                }
                if (dogelu) { vx = gelu_exact(vx); vy = gelu_exact(vy); }
                if (C)
                    *(float2*)(C + (size_t)r * N + col) = make_float2(vx, vy);
                if (Ch)
                    *(__half2*)(Ch + (size_t)r * N + col) = __floats2half2_rn(vx, vy);
            }
        }
    }
}

// ---------------- layernorm: fp32 out + fp16 out ----------------
__global__ __launch_bounds__(128) void ln_kernel(
    const float* __restrict__ in, float* __restrict__ out, __half* __restrict__ outh,
    const float* __restrict__ gamma, const float* __restrict__ beta)
{
    __shared__ float red[8];
    int row = blockIdx.x;
    int t = threadIdx.x;
    float4 v = ((const float4*)(in + (size_t)row * DEC))[t];
    float s  = v.x + v.y + v.z + v.w;
    float sq = v.x * v.x + v.y * v.y + v.z * v.z + v.w * v.w;
    #pragma unroll
    for (int off = 16; off > 0; off >>= 1) {
        s  += __shfl_xor_sync(0xffffffff, s,  off);
        sq += __shfl_xor_sync(0xffffffff, sq, off);
    }
    int w = t >> 5;
    if ((t & 31) == 0) { red[w] = s; red[4 + w] = sq; }
    __syncthreads();
    s  = red[0] + red[1] + red[2] + red[3];
    sq = red[4] + red[5] + red[6] + red[7];
    float mu = s * (1.0f / DEC);
    float var = sq * (1.0f / DEC) - mu * mu;
    float rstd = rsqrtf(var + 1e-5f);
    float4 g = ((const float4*)gamma)[t];
    float4 b = ((const float4*)beta)[t];
    float4 o;
    o.x = (v.x - mu) * rstd * g.x + b.x;
    o.y = (v.y - mu) * rstd * g.y + b.y;
    o.z = (v.z - mu) * rstd * g.z + b.z;
    o.w = (v.w - mu) * rstd * g.w + b.w;
    ((float4*)(out + (size_t)row * DEC))[t] = o;
    __half2* hh = (__half2*)(outh + (size_t)row * DEC);
    hh[t * 2 + 0] = __floats2half2_rn(o.x, o.y);
    hh[t * 2 + 1] = __floats2half2_rn(o.z, o.w);
}

// ---------------- attention (fp16 qkv input; 2 query-blocks per (b,h)) ----------------
#define KSTRIDE 33
#define SM_K 0
#define SM_V (NPATCH * KSTRIDE)
#define SM_P (SM_V + NPATCH * HD)
#define ATTN_SMEM ((SM_P + 8 * NPATCH) * 4)

__global__ __launch_bounds__(256) void attn_kernel() {
    extern __shared__ float smf[];
    float* Ksm = smf + SM_K;
    float* Vsm = smf + SM_V;
    float* Psm = smf + SM_P;

    int bh = blockIdx.x >> 1;
    int qhalf = blockIdx.x & 1;
    int b = bh >> 4;
    int h = bh & 15;
    const __half* qkv = g_qkvh + (size_t)b * (NPATCH * 3 * DEC);
    int tid = threadIdx.x;

    for (int idx = tid; idx < NPATCH * HD; idx += 256) {
        int j = idx >> 5, d = idx & 31;
        Ksm[j * KSTRIDE + d] = __half2float(qkv[j * (3 * DEC) + DEC     + h * HD + d]);
        Vsm[j * HD      + d] = __half2float(qkv[j * (3 * DEC) + 2 * DEC + h * HD + d]);
    }
    __syncthreads();

    int warp = tid >> 5, lane = tid & 31;
    const float scale = 0.17677669529663687f;
    const int qstart = qhalf * 98;
    const int qend = qstart + 98;

    for (int i = qstart + warp; i < qend; i += 8) {
        const __half* q = qkv + i * (3 * DEC) + h * HD;
        float qr[HD];
        #pragma unroll
        for (int kk = 0; kk < HD; kk++) qr[kk] = __half2float(q[kk]);

        float s[7];
        float mx = -1e30f;
        #pragma unroll
        for (int jj = 0; jj < 7; jj++) {
            int j = jj * 32 + lane;
            float acc = -1e30f;
            if (j < NPATCH) {
                acc = 0.f;
                #pragma unroll
                for (int kk = 0; kk < HD; kk++) acc += qr[kk] * Ksm[j * KSTRIDE + kk];
                acc *= scale;
            }
            s[jj] = acc;
            mx = fmaxf(mx, acc);
        }
        #pragma unroll
        for (int off = 16; off > 0; off >>= 1)
            mx = fmaxf(mx, __shfl_xor_sync(0xffffffff, mx, off));

        float sum = 0.f;
        #pragma unroll
        for (int jj = 0; jj < 7; jj++) {
            int j = jj * 32 + lane;
            float p = (j < NPATCH) ? __expf(s[jj] - mx) : 0.f;
            if (j < NPATCH) Psm[warp * NPATCH + j] = p;
            sum += p;
        }
        #pragma unroll
        for (int off = 16; off > 0; off >>= 1)
            sum += __shfl_xor_sync(0xffffffff, sum, off);
        float inv = 1.0f / sum;
        __syncwarp();

        const float* pp = Psm + warp * NPATCH;
        float a0 = 0.f, a1 = 0.f, a2 = 0.f, a3 = 0.f;
        for (int j = 0; j < NPATCH; j += 4) {
            a0 += pp[j]     * Vsm[j * HD + lane];
            a1 += pp[j + 1] * Vsm[(j + 1) * HD + lane];
            a2 += pp[j + 2] * Vsm[(j + 2) * HD + lane];
            a3 += pp[j + 3] * Vsm[(j + 3) * HD + lane];
        }
        float acc = (a0 + a1) + (a2 + a3);
        g_attnh[((size_t)b * NPATCH + i) * DEC + h * HD + lane] = __float2half_rn(acc * inv);
        __syncwarp();
    }
}

// ---------------- host launchers ----------------
static inline void launch_gemm(const __half* A, const __half* Wt, const float* bias,
                               const float* resid, float* C, __half* Ch,
                               int M, int N, int K, int flags) {
    dim3 grid(N / BN, (M + BM - 1) / BM);
    gemm_tc_kernel<<<grid, 512, GEMM_SMEM>>>(A, Wt, bias, resid, C, Ch, M, N, K, flags);
}

extern "C" void kernel_launch(void* const* d_in, const int* in_sizes, int n_in,
                              void* d_out, int out_size) {
    const float* x          = (const float*)d_in[0];
    const int*   mask       = (const int*)  d_in[1];
    const float* Wp         = (const float*)d_in[3];
    const float* bp         = (const float*)d_in[4];
    const float* We2d       = (const float*)d_in[5];
    const float* be2d       = (const float*)d_in[6];
    const float* mask_token = (const float*)d_in[7];
    const float* pos_embed  = (const float*)d_in[8];
    const float* Wqkv       = (const float*)d_in[9];
    const float* bqkv       = (const float*)d_in[10];
    const float* Wo         = (const float*)d_in[11];
    const float* bo         = (const float*)d_in[12];
    const float* ln1g       = (const float*)d_in[13];
    const float* ln1b       = (const float*)d_in[14];
    const float* W1         = (const float*)d_in[15];
    const float* b1         = (const float*)d_in[16];
    const float* W2         = (const float*)d_in[17];
    const float* b2         = (const float*)d_in[18];
    const float* ln2g       = (const float*)d_in[19];
    const float* ln2b       = (const float*)d_in[20];
    const float* Wr         = (const float*)d_in[21];
    const float* br         = (const float*)d_in[22];

    float* out = (float*)d_out;
    float* rec = out;
    float* enc = out + (size_t)ROWS_N * OUTD;

    __half *p_patchh, *p_ench, *p_hh, *p_attnh, *p_qkvh, *p_ffnh, *p_wh;
    float  *p_dec, *p_h, *p_tmp;
    cudaGetSymbolAddress((void**)&p_patchh, g_patchh);
    cudaGetSymbolAddress((void**)&p_ench,   g_ench);
    cudaGetSymbolAddress((void**)&p_dec,    g_dec);
    cudaGetSymbolAddress((void**)&p_h,      g_h);
    cudaGetSymbolAddress((void**)&p_hh,     g_hh);
    cudaGetSymbolAddress((void**)&p_tmp,    g_tmp);
    cudaGetSymbolAddress((void**)&p_attnh,  g_attnh);
    cudaGetSymbolAddress((void**)&p_qkvh,   g_qkvh);
    cudaGetSymbolAddress((void**)&p_ffnh,   g_ffnh);
    cudaGetSymbolAddress((void**)&p_wh,     g_wh);

    cudaFuncSetAttribute(attn_kernel, cudaFuncAttributeMaxDynamicSharedMemorySize, ATTN_SMEM);
    cudaFuncSetAttribute(gemm_tc_kernel, cudaFuncAttributeMaxDynamicSharedMemorySize, GEMM_SMEM);

    // prep: one fused transpose + scan + patchify
    fused_tr<<<28800, dim3(32, 8)>>>(Wp, We2d, Wqkv, Wo, W1, W2, Wr, p_wh);
    scan_kernel<<<1, 64>>>(mask);
    patchify_kernel<<<ROWS_V, 256>>>(x);

    launch_gemm(p_patchh, p_wh + WT_WP, bp, nullptr, enc, p_ench, ROWS_V, ENC, OUTD, 0);
    launch_gemm(p_ench, p_wh + WT_E2D, be2d, nullptr, p_dec, nullptr, ROWS_V, DEC, ENC, 0);
    assemble_kernel<<<ROWS_N, 128>>>(mask_token, pos_embed);

    for (int l = 0; l < NL; l++) {
        const __half* wh_qkv = p_wh + WT_QKV + (size_t)l * 3 * DEC * DEC;
        const __half* wh_o   = p_wh + WT_O   + (size_t)l * DEC * DEC;
        const __half* wh_1   = p_wh + WT_W1  + (size_t)l * DEC * FFN;
        const __half* wh_2   = p_wh + WT_W2  + (size_t)l * FFN * DEC;
        const float* bq  = bqkv + (size_t)l * 3 * DEC;
        const float* bol = bo   + (size_t)l * DEC;
        const float* b1l = b1   + (size_t)l * FFN;
        const float* b2l = b2   + (size_t)l * DEC;

        launch_gemm(p_hh, wh_qkv, bq, nullptr, nullptr, p_qkvh, ROWS_N, 3 * DEC, DEC, 0);
        attn_kernel<<<B_ * NH * 2, 256, ATTN_SMEM>>>();
        launch_gemm(p_attnh, wh_o, bol, p_h, p_tmp, nullptr, ROWS_N, DEC, DEC, 0);
        ln_kernel<<<ROWS_N, 128>>>(p_tmp, p_h, p_hh, ln1g + l * DEC, ln1b + l * DEC);
        launch_gemm(p_hh, wh_1, b1l, nullptr, nullptr, p_ffnh, ROWS_N, FFN, DEC, FLAG_GELU);
        launch_gemm(p_ffnh, wh_2, b2l, p_h, p_tmp, nullptr, ROWS_N, DEC, FFN, 0);
        ln_kernel<<<ROWS_N, 128>>>(p_tmp, p_h, p_hh, ln2g + l * DEC, ln2b + l * DEC);
    }

    launch_gemm(p_hh, p_wh + WT_R, br, nullptr, rec, nullptr, ROWS_N, OUTD, DEC, 0);
}

// round 13
// speedup vs baseline: 1.0524x; 1.0524x over previous
#include <cuda_runtime.h>
#include <cuda_fp16.h>
#include <cstdint>
#include <math.h>

// ---------------- problem constants ----------------
#define B_      64
#define V_      49
#define NPATCH  196
#define CIN     12
#define PSZ     16
#define IMG     224
#define ENC     768
#define DEC     512
#define NL      8
#define NH      16
#define HD      32
#define FFN     2048
#define OUTD    3072
#define ROWS_V  (B_ * V_)       // 3136
#define ROWS_N  (B_ * NPATCH)   // 12544

// ---------------- scratch ----------------
__device__ __half g_patchh[ROWS_V * OUTD];
__device__ __half g_ench  [ROWS_V * ENC];
__device__ float  g_dec   [ROWS_V * DEC];
__device__ float  g_h     [ROWS_N * DEC];
__device__ __half g_hh    [ROWS_N * DEC];
__device__ float  g_tmp   [ROWS_N * DEC];
__device__ __half g_attnh [ROWS_N * DEC];
__device__ __half g_qkvh  [ROWS_N * 3 * DEC];
__device__ __half g_ffnh  [ROWS_N * FFN];
__device__ __half g_wh    [29491200];        // fp16 weights, TRANSPOSED to [N,K]
__device__ int    g_visidx[B_ * V_];
__device__ int    g_src   [B_ * NPATCH];

// weight-scratch offsets (halfs)
#define WT_WP   0
#define WT_E2D  2359296
#define WT_QKV  2752512
#define WT_O    9043968
#define WT_W1   11141120
#define WT_W2   19529728
#define WT_R    27918336

// ---------------- helpers ----------------
__device__ __forceinline__ float gelu_exact(float v) {
    return 0.5f * v * (1.0f + erff(v * 0.7071067811865476f));
}
__device__ __forceinline__ void cp_async16(void* smem_dst, const void* gmem_src, bool pred) {
    uint32_t saddr = (uint32_t)__cvta_generic_to_shared(smem_dst);
    int sz = pred ? 16 : 0;
    asm volatile("cp.async.cg.shared.global [%0], [%1], 16, %2;\n"
                 :: "r"(saddr), "l"(gmem_src), "r"(sz));
}
__device__ __forceinline__ void mma_f16(float* c, const uint32_t* a, const uint32_t* b) {
    asm volatile(
        "mma.sync.aligned.m16n8k16.row.col.f32.f16.f16.f32 "
        "{%0,%1,%2,%3}, {%4,%5,%6,%7}, {%8,%9}, {%0,%1,%2,%3};"
        : "+f"(c[0]), "+f"(c[1]), "+f"(c[2]), "+f"(c[3])
        : "r"(a[0]), "r"(a[1]), "r"(a[2]), "r"(a[3]), "r"(b[0]), "r"(b[1]));
}
__device__ __forceinline__ void ldsm4(uint32_t* r, uint32_t saddr) {
    asm volatile("ldmatrix.sync.aligned.m8n8.x4.shared.b16 {%0,%1,%2,%3}, [%4];"
                 : "=r"(r[0]), "=r"(r[1]), "=r"(r[2]), "=r"(r[3]) : "r"(saddr));
}

// ---------------- fused weight prep: all transposes in one kernel ----------------
__global__ void fused_tr(const float* __restrict__ Wp, const float* __restrict__ We2d,
                         const float* __restrict__ Wqkv, const float* __restrict__ Wo,
                         const float* __restrict__ W1, const float* __restrict__ W2,
                         const float* __restrict__ Wr, __half* __restrict__ wh) {
    __shared__ float t[32][33];
    int tile = blockIdx.x;
    const float* src; __half* dst; int K, N;
    if (tile < 2304)        { src = Wp;   dst = wh + WT_WP;  K = OUTD; N = ENC; }
    else if (tile < 2688)   { tile -= 2304; src = We2d; dst = wh + WT_E2D; K = ENC; N = DEC; }
    else if (tile < 8832)   { tile -= 2688; int l = tile / 768;  tile -= l * 768;
                              src = Wqkv + (size_t)l * DEC * 3 * DEC;
                              dst = wh + WT_QKV + (size_t)l * 3 * DEC * DEC; K = DEC; N = 3 * DEC; }
    else if (tile < 10880)  { tile -= 8832; int l = tile / 256;  tile -= l * 256;
                              src = Wo + (size_t)l * DEC * DEC;
                              dst = wh + WT_O + (size_t)l * DEC * DEC; K = DEC; N = DEC; }
    else if (tile < 19072)  { tile -= 10880; int l = tile / 1024; tile -= l * 1024;
                              src = W1 + (size_t)l * DEC * FFN;
                              dst = wh + WT_W1 + (size_t)l * DEC * FFN; K = DEC; N = FFN; }
    else if (tile < 27264)  { tile -= 19072; int l = tile / 1024; tile -= l * 1024;
                              src = W2 + (size_t)l * FFN * DEC;
                              dst = wh + WT_W2 + (size_t)l * FFN * DEC; K = FFN; N = DEC; }
    else                    { tile -= 27264; src = Wr; dst = wh + WT_R; K = DEC; N = OUTD; }
    int ntx = N / 32;
    int kb = (tile / ntx) * 32, nb = (tile % ntx) * 32;
    #pragma unroll
    for (int i = 0; i < 4; i++)
        t[threadIdx.y + 8 * i][threadIdx.x] =
            src[(size_t)(kb + threadIdx.y + 8 * i) * N + nb + threadIdx.x];
    __syncthreads();
    #pragma unroll
    for (int i = 0; i < 4; i++)
        dst[(size_t)(nb + threadIdx.y + 8 * i) * K + kb + threadIdx.x] =
            __float2half_rn(t[threadIdx.x][threadIdx.y + 8 * i]);
}

// ---------------- mask scan ----------------
__global__ void scan_kernel(const int* __restrict__ mask) {
    int b = threadIdx.x;
    if (b >= B_) return;
    int cnt = 0;
    for (int n = 0; n < NPATCH; n++) {
        int m = mask[b * NPATCH + n];
        if (m == 0) {
            if (cnt < V_) g_visidx[b * V_ + cnt] = n;
            g_src[b * NPATCH + n] = (cnt < V_) ? cnt : (V_ - 1);
            cnt++;
        } else {
            g_src[b * NPATCH + n] = -1;
        }
    }
    for (int c = cnt; c < V_; c++) g_visidx[b * V_ + c] = 0;
}

// ---------------- patchify -> fp16 ----------------
__global__ void patchify_kernel(const float* __restrict__ x) {
    int r  = blockIdx.x;
    int b  = r / V_;
    int n  = g_visidx[r];
    int hp = n / (IMG / PSZ);
    int wp = n % (IMG / PSZ);
    for (int f = threadIdx.x; f < OUTD; f += blockDim.x) {
        int c  = f >> 8;
        int ph = (f >> 4) & 15;
        int pw = f & 15;
        float v = x[((b * CIN + c) * IMG + hp * PSZ + ph) * IMG + wp * PSZ + pw];
        g_patchh[(size_t)r * OUTD + f] = __float2half_rn(v);
    }
}

// ---------------- assemble ----------------
__global__ void assemble_kernel(const float* __restrict__ mask_token,
                                const float* __restrict__ pos_embed) {
    int row = blockIdx.x;
    int b = row / NPATCH;
    int n = row % NPATCH;
    int s = g_src[row];
    const float4* src = (s >= 0)
        ? (const float4*)&g_dec[(b * V_ + s) * DEC]
        : (const float4*)mask_token;
    const float4* pos = (const float4*)&pos_embed[n * DEC];
    int t = threadIdx.x;
    float4 a = src[t], p = pos[t];
    float4 v = make_float4(a.x + p.x, a.y + p.y, a.z + p.z, a.w + p.w);
    ((float4*)&g_h[(size_t)row * DEC])[t] = v;
    __half2* hh = (__half2*)&g_hh[(size_t)row * DEC];
    hh[t * 2 + 0] = __floats2half2_rn(v.x, v.y);
    hh[t * 2 + 1] = __floats2half2_rn(v.z, v.w);
}

// ---------------- fp16 tensor-core GEMM: BK=64, 512 threads, 16 warps ----
#define BM 128
#define BN 128
#define BK 64
#define STRH 72                          // halfs per smem row (64 + pad 8) = 144 B
#define TILEH (128 * STRH)               // 9216 halfs per tile
#define STAGEH (2 * TILEH)               // A + B
#define NSTAGE 2
#define GEMM_SMEM (NSTAGE * STAGEH * 2)  // 73728 B
#define FLAG_GELU 1

__device__ __forceinline__ void gemm_load_stage(
    const __half* __restrict__ A, const __half* __restrict__ Wt,
    __half* sm, int s, int c, int bm, int bn, int M, int K, int t)
{
    __half* base = sm + s * STAGEH;
    int k0 = c * BK;
    #pragma unroll
    for (int i = 0; i < 4; i++) {
        int idx = t + (i << 9);              // 0..2047 (16B = 8 halfs each)
        int part = idx >> 10;                // 0 = A, 1 = B
        int sub  = idx & 1023;
        int row  = sub >> 3;                 // 0..127
        int c8   = sub & 7;                  // 0..7
        const __half* src;
        int ok = 1;
        if (part == 0) {
            int gr = bm + row;
            if (gr >= M) { ok = 0; gr = M - 1; }
            src = A + (size_t)gr * K + k0 + c8 * 8;
        } else {
            src = Wt + (size_t)(bn + row) * K + k0 + c8 * 8;
        }
        cp_async16(base + part * TILEH + row * STRH + c8 * 8, src, ok);
    }
    asm volatile("cp.async.commit_group;\n");
}

__global__ __launch_bounds__(512, 2) void gemm_tc_kernel(
    const __half* __restrict__ A, const __half* __restrict__ Wt,
    const float* __restrict__ bias, const float* __restrict__ resid,
    float* __restrict__ C, __half* __restrict__ Ch,
    int M, int N, int K, int flags)
{
    extern __shared__ __half sm[];

    const int t = threadIdx.x;
    const int bn = blockIdx.x * BN;
    const int bm = blockIdx.y * BM;
    const int warp = t >> 5, lane = t & 31;
    const int wm = warp >> 2, wn = warp & 3;     // 4 x 4 warps, warp tile 32x32
    const int lq = lane >> 2, lr = lane & 3;
    const int g  = lane >> 3;                    // ldmatrix group 0..3
    const int gr = lane & 7;

    float acc[2][4][4] = {};

    const int nch = K / BK;
    gemm_load_stage(A, Wt, sm, 0, 0, bm, bn, M, K, t);

    // hoisted per-stage ldmatrix bases (bytes)
    const int a_off = (wm * 32 + (g & 1) * 8 + gr) * STRH + (g >> 1) * 8;
    const int b_off = (wn * 32 + g * 8 + gr) * STRH;
    uint32_t a_base0 = (uint32_t)__cvta_generic_to_shared(sm + a_off);
    uint32_t b_base0 = (uint32_t)__cvta_generic_to_shared(sm + TILEH + b_off);
    const uint32_t stage_b = STAGEH * 2;

    for (int c = 0; c < nch; c++) {
        int s = c & 1;
        if (c + 1 < nch) {
            gemm_load_stage(A, Wt, sm, s ^ 1, c + 1, bm, bn, M, K, t);
            asm volatile("cp.async.wait_group 1;\n");
        } else {
            asm volatile("cp.async.wait_group 0;\n");
        }
        __syncthreads();

        uint32_t a_base = a_base0 + s * stage_b;
        uint32_t b_base = b_base0 + s * stage_b;

        #pragma unroll
        for (int ks = 0; ks < 4; ks++) {          // four k16 steps per BK=64 chunk
            const int kh = ks * 16;
            uint32_t af[2][4];
            uint32_t b0[4], b1[4];
            #pragma unroll
            for (int mi = 0; mi < 2; mi++)
                ldsm4(af[mi], a_base + (mi * 16 * STRH + kh) * 2);
            ldsm4(b0, b_base + (kh + 0) * 2);
            ldsm4(b1, b_base + (kh + 8) * 2);
            #pragma unroll
            for (int mi = 0; mi < 2; mi++)
                #pragma unroll
                for (int ni = 0; ni < 4; ni++) {
                    uint32_t bf[2] = { b0[ni], b1[ni] };
                    mma_f16(acc[mi][ni], af[mi], bf);
                }
        }
        __syncthreads();
    }

    const bool dogelu = (flags & FLAG_GELU) != 0;

    #pragma unroll
    for (int mi = 0; mi < 2; mi++) {
        int r0 = bm + wm * 32 + mi * 16 + lq;
        #pragma unroll
        for (int ni = 0; ni < 4; ni++) {
            int col = bn + wn * 32 + ni * 8 + lr * 2;
            float bx = bias[col], by = bias[col + 1];
            float* a4 = acc[mi][ni];
            #pragma unroll
            for (int half = 0; half < 2; half++) {
                int r = r0 + half * 8;
                if (r >= M) continue;
                float vx = a4[half * 2 + 0] + bx;
                float vy = a4[half * 2 + 1] + by;
                if (resid) {
                    const float* rr = resid + (size_t)r * N + col;
                    vx += rr[0]; vy += rr[1];
                }
                if (dogelu) { vx = gelu_exact(vx); vy = gelu_exact(vy); }
                if (C)
                    *(float2*)(C + (size_t)r * N + col) = make_float2(vx, vy);
                if (Ch)
                    *(__half2*)(Ch + (size_t)r * N + col) = __floats2half2_rn(vx, vy);
            }
        }
    }
}

// ---------------- layernorm: fp32 out + fp16 out ----------------
__global__ __launch_bounds__(128) void ln_kernel(
    const float* __restrict__ in, float* __restrict__ out, __half* __restrict__ outh,
    const float* __restrict__ gamma, const float* __restrict__ beta)
{
    __shared__ float red[8];
    int row = blockIdx.x;
    int t = threadIdx.x;
    float4 v = ((const float4*)(in + (size_t)row * DEC))[t];
    float s  = v.x + v.y + v.z + v.w;
    float sq = v.x * v.x + v.y * v.y + v.z * v.z + v.w * v.w;
    #pragma unroll
    for (int off = 16; off > 0; off >>= 1) {
        s  += __shfl_xor_sync(0xffffffff, s,  off);
        sq += __shfl_xor_sync(0xffffffff, sq, off);
    }
    int w = t >> 5;
    if ((t & 31) == 0) { red[w] = s; red[4 + w] = sq; }
    __syncthreads();
    s  = red[0] + red[1] + red[2] + red[3];
    sq = red[4] + red[5] + red[6] + red[7];
    float mu = s * (1.0f / DEC);
    float var = sq * (1.0f / DEC) - mu * mu;
    float rstd = rsqrtf(var + 1e-5f);
    float4 g = ((const float4*)gamma)[t];
    float4 b = ((const float4*)beta)[t];
    float4 o;
    o.x = (v.x - mu) * rstd * g.x + b.x;
    o.y = (v.y - mu) * rstd * g.y + b.y;
    o.z = (v.z - mu) * rstd * g.z + b.z;
    o.w = (v.w - mu) * rstd * g.w + b.w;
    ((float4*)(out + (size_t)row * DEC))[t] = o;
    __half2* hh = (__half2*)(outh + (size_t)row * DEC);
    hh[t * 2 + 0] = __floats2half2_rn(o.x, o.y);
    hh[t * 2 + 1] = __floats2half2_rn(o.z, o.w);
}

// ---------------- attention (fp16 qkv input; 2 query-blocks per (b,h)) ----------------
#define KSTRIDE 33
#define SM_K 0
#define SM_V (NPATCH * KSTRIDE)
#define SM_P (SM_V + NPATCH * HD)
#define ATTN_SMEM ((SM_P + 8 * NPATCH) * 4)

__global__ __launch_bounds__(256) void attn_kernel() {
    extern __shared__ float smf[];
    float* Ksm = smf + SM_K;
    float* Vsm = smf + SM_V;
    float* Psm = smf + SM_P;

    int bh = blockIdx.x >> 1;
    int qhalf = blockIdx.x & 1;
    int b = bh >> 4;
    int h = bh & 15;
    const __half* qkv = g_qkvh + (size_t)b * (NPATCH * 3 * DEC);
    int tid = threadIdx.x;

    for (int idx = tid; idx < NPATCH * HD; idx += 256) {
        int j = idx >> 5, d = idx & 31;
        Ksm[j * KSTRIDE + d] = __half2float(qkv[j * (3 * DEC) + DEC     + h * HD + d]);
        Vsm[j * HD      + d] = __half2float(qkv[j * (3 * DEC) + 2 * DEC + h * HD + d]);
    }
    __syncthreads();

    int warp = tid >> 5, lane = tid & 31;
    const float scale = 0.17677669529663687f;
    const int qstart = qhalf * 98;
    const int qend = qstart + 98;

    for (int i = qstart + warp; i < qend; i += 8) {
        const __half* q = qkv + i * (3 * DEC) + h * HD;
        float qr[HD];
        #pragma unroll
        for (int kk = 0; kk < HD; kk++) qr[kk] = __half2float(q[kk]);

        float s[7];
        float mx = -1e30f;
        #pragma unroll
        for (int jj = 0; jj < 7; jj++) {
            int j = jj * 32 + lane;
            float acc = -1e30f;
            if (j < NPATCH) {
                acc = 0.f;
                #pragma unroll
                for (int kk = 0; kk < HD; kk++) acc += qr[kk] * Ksm[j * KSTRIDE + kk];
                acc *= scale;
            }
            s[jj] = acc;
            mx = fmaxf(mx, acc);
        }
        #pragma unroll
        for (int off = 16; off > 0; off >>= 1)
            mx = fmaxf(mx, __shfl_xor_sync(0xffffffff, mx, off));

        float sum = 0.f;
        #pragma unroll
        for (int jj = 0; jj < 7; jj++) {
            int j = jj * 32 + lane;
            float p = (j < NPATCH) ? __expf(s[jj] - mx) : 0.f;
            if (j < NPATCH) Psm[warp * NPATCH + j] = p;
            sum += p;
        }
        #pragma unroll
        for (int off = 16; off > 0; off >>= 1)
            sum += __shfl_xor_sync(0xffffffff, sum, off);
        float inv = 1.0f / sum;
        __syncwarp();

        const float* pp = Psm + warp * NPATCH;
        float a0 = 0.f, a1 = 0.f, a2 = 0.f, a3 = 0.f;
        for (int j = 0; j < NPATCH; j += 4) {
            a0 += pp[j]     * Vsm[j * HD + lane];
            a1 += pp[j + 1] * Vsm[(j + 1) * HD + lane];
            a2 += pp[j + 2] * Vsm[(j + 2) * HD + lane];
            a3 += pp[j + 3] * Vsm[(j + 3) * HD + lane];
        }
        float acc = (a0 + a1) + (a2 + a3);
        g_attnh[((size_t)b * NPATCH + i) * DEC + h * HD + lane] = __float2half_rn(acc * inv);
        __syncwarp();
    }
}

// ---------------- host launchers ----------------
static inline void launch_gemm(const __half* A, const __half* Wt, const float* bias,
                               const float* resid, float* C, __half* Ch,
                               int M, int N, int K, int flags) {
    dim3 grid(N / BN, (M + BM - 1) / BM);
    gemm_tc_kernel<<<grid, 512, GEMM_SMEM>>>(A, Wt, bias, resid, C, Ch, M, N, K, flags);
}

extern "C" void kernel_launch(void* const* d_in, const int* in_sizes, int n_in,
                              void* d_out, int out_size) {
    const float* x          = (const float*)d_in[0];
    const int*   mask       = (const int*)  d_in[1];
    const float* Wp         = (const float*)d_in[3];
    const float* bp         = (const float*)d_in[4];
    const float* We2d       = (const float*)d_in[5];
    const float* be2d       = (const float*)d_in[6];
    const float* mask_token = (const float*)d_in[7];
    const float* pos_embed  = (const float*)d_in[8];
    const float* Wqkv       = (const float*)d_in[9];
    const float* bqkv       = (const float*)d_in[10];
    const float* Wo         = (const float*)d_in[11];
    const float* bo         = (const float*)d_in[12];
    const float* ln1g       = (const float*)d_in[13];
    const float* ln1b       = (const float*)d_in[14];
    const float* W1         = (const float*)d_in[15];
    const float* b1         = (const float*)d_in[16];
    const float* W2         = (const float*)d_in[17];
    const float* b2         = (const float*)d_in[18];
    const float* ln2g       = (const float*)d_in[19];
    const float* ln2b       = (const float*)d_in[20];
    const float* Wr         = (const float*)d_in[21];
    const float* br         = (const float*)d_in[22];

    float* out = (float*)d_out;
    float* rec = out;
    float* enc = out + (size_t)ROWS_N * OUTD;

    __half *p_patchh, *p_ench, *p_hh, *p_attnh, *p_qkvh, *p_ffnh, *p_wh;
    float  *p_dec, *p_h, *p_tmp;
    cudaGetSymbolAddress((void**)&p_patchh, g_patchh);
    cudaGetSymbolAddress((void**)&p_ench,   g_ench);
    cudaGetSymbolAddress((void**)&p_dec,    g_dec);
    cudaGetSymbolAddress((void**)&p_h,      g_h);
    cudaGetSymbolAddress((void**)&p_hh,     g_hh);
    cudaGetSymbolAddress((void**)&p_tmp,    g_tmp);
    cudaGetSymbolAddress((void**)&p_attnh,  g_attnh);
    cudaGetSymbolAddress((void**)&p_qkvh,   g_qkvh);
    cudaGetSymbolAddress((void**)&p_ffnh,   g_ffnh);
    cudaGetSymbolAddress((void**)&p_wh,     g_wh);

    cudaFuncSetAttribute(attn_kernel, cudaFuncAttributeMaxDynamicSharedMemorySize, ATTN_SMEM);
    cudaFuncSetAttribute(gemm_tc_kernel, cudaFuncAttributeMaxDynamicSharedMemorySize, GEMM_SMEM);

    fused_tr<<<28800, dim3(32, 8)>>>(Wp, We2d, Wqkv, Wo, W1, W2, Wr, p_wh);
    scan_kernel<<<1, 64>>>(mask);
    patchify_kernel<<<ROWS_V, 256>>>(x);

    launch_gemm(p_patchh, p_wh + WT_WP, bp, nullptr, enc, p_ench, ROWS_V, ENC, OUTD, 0);
    launch_gemm(p_ench, p_wh + WT_E2D, be2d, nullptr, p_dec, nullptr, ROWS_V, DEC, ENC, 0);
    assemble_kernel<<<ROWS_N, 128>>>(mask_token, pos_embed);

    for (int l = 0; l < NL; l++) {
        const __half* wh_qkv = p_wh + WT_QKV + (size_t)l * 3 * DEC * DEC;
        const __half* wh_o   = p_wh + WT_O   + (size_t)l * DEC * DEC;
        const __half* wh_1   = p_wh + WT_W1  + (size_t)l * DEC * FFN;
        const __half* wh_2   = p_wh + WT_W2  + (size_t)l * FFN * DEC;
        const float* bq  = bqkv + (size_t)l * 3 * DEC;
        const float* bol = bo   + (size_t)l * DEC;
        const float* b1l = b1   + (size_t)l * FFN;
        const float* b2l = b2   + (size_t)l * DEC;

        launch_gemm(p_hh, wh_qkv, bq, nullptr, nullptr, p_qkvh, ROWS_N, 3 * DEC, DEC, 0);
        attn_kernel<<<B_ * NH * 2, 256, ATTN_SMEM>>>();
        launch_gemm(p_attnh, wh_o, bol, p_h, p_tmp, nullptr, ROWS_N, DEC, DEC, 0);
        ln_kernel<<<ROWS_N, 128>>>(p_tmp, p_h, p_hh, ln1g + l * DEC, ln1b + l * DEC);
        launch_gemm(p_hh, wh_1, b1l, nullptr, nullptr, p_ffnh, ROWS_N, FFN, DEC, FLAG_GELU);
        launch_gemm(p_ffnh, wh_2, b2l, p_h, p_tmp, nullptr, ROWS_N, DEC, FFN, 0);
        ln_kernel<<<ROWS_N, 128>>>(p_tmp, p_h, p_hh, ln2g + l * DEC, ln2b + l * DEC);
    }

    launch_gemm(p_hh, p_wh + WT_R, br, nullptr, rec, nullptr, ROWS_N, OUTD, DEC, 0);
}

// round 14
// speedup vs baseline: 1.0645x; 1.0116x over previous
#include <cuda_runtime.h>
#include <cuda_fp16.h>
#include <cstdint>
#include <math.h>

// ---------------- problem constants ----------------
#define B_      64
#define V_      49
#define NPATCH  196
#define CIN     12
#define PSZ     16
#define IMG     224
#define ENC     768
#define DEC     512
#define NL      8
#define NH      16
#define HD      32
#define FFN     2048
#define OUTD    3072
#define ROWS_V  (B_ * V_)       // 3136
#define ROWS_N  (B_ * NPATCH)   // 12544

// ---------------- scratch ----------------
__device__ __half g_patchh[ROWS_V * OUTD];
__device__ __half g_ench  [ROWS_V * ENC];
__device__ float  g_dec   [ROWS_V * DEC];
__device__ float  g_h     [ROWS_N * DEC];
__device__ __half g_hh    [ROWS_N * DEC];
__device__ float  g_tmp   [ROWS_N * DEC];
__device__ __half g_attnh [ROWS_N * DEC];
__device__ __half g_qkvh  [ROWS_N * 3 * DEC];
__device__ __half g_ffnh  [ROWS_N * FFN];
__device__ __half g_wh    [29491200];        // fp16 weights, TRANSPOSED to [N,K]
__device__ int    g_visidx[B_ * V_];
__device__ int    g_src   [B_ * NPATCH];

// weight-scratch offsets (halfs)
#define WT_WP   0
#define WT_E2D  2359296
#define WT_QKV  2752512
#define WT_O    9043968
#define WT_W1   11141120
#define WT_W2   19529728
#define WT_R    27918336

// ---------------- helpers ----------------
__device__ __forceinline__ float gelu_exact(float v) {
    return 0.5f * v * (1.0f + erff(v * 0.7071067811865476f));
}
__device__ __forceinline__ void cp_async16u(uint32_t saddr, const void* gsrc, int sz) {
    asm volatile("cp.async.cg.shared.global [%0], [%1], 16, %2;\n"
                 :: "r"(saddr), "l"(gsrc), "r"(sz));
}
__device__ __forceinline__ void mma_f16(float* c, const uint32_t* a, const uint32_t* b) {
    asm volatile(
        "mma.sync.aligned.m16n8k16.row.col.f32.f16.f16.f32 "
        "{%0,%1,%2,%3}, {%4,%5,%6,%7}, {%8,%9}, {%0,%1,%2,%3};"
        : "+f"(c[0]), "+f"(c[1]), "+f"(c[2]), "+f"(c[3])
        : "r"(a[0]), "r"(a[1]), "r"(a[2]), "r"(a[3]), "r"(b[0]), "r"(b[1]));
}
__device__ __forceinline__ void ldsm4(uint32_t* r, uint32_t saddr) {
    asm volatile("ldmatrix.sync.aligned.m8n8.x4.shared.b16 {%0,%1,%2,%3}, [%4];"
                 : "=r"(r[0]), "=r"(r[1]), "=r"(r[2]), "=r"(r[3]) : "r"(saddr));
}

// ---------------- fused weight prep: all transposes in one kernel ----------------
__global__ void fused_tr(const float* __restrict__ Wp, const float* __restrict__ We2d,
                         const float* __restrict__ Wqkv, const float* __restrict__ Wo,
                         const float* __restrict__ W1, const float* __restrict__ W2,
                         const float* __restrict__ Wr, __half* __restrict__ wh) {
    __shared__ float t[32][33];
    int tile = blockIdx.x;
    const float* src; __half* dst; int K, N;
    if (tile < 2304)        { src = Wp;   dst = wh + WT_WP;  K = OUTD; N = ENC; }
    else if (tile < 2688)   { tile -= 2304; src = We2d; dst = wh + WT_E2D; K = ENC; N = DEC; }
    else if (tile < 8832)   { tile -= 2688; int l = tile / 768;  tile -= l * 768;
                              src = Wqkv + (size_t)l * DEC * 3 * DEC;
                              dst = wh + WT_QKV + (size_t)l * 3 * DEC * DEC; K = DEC; N = 3 * DEC; }
    else if (tile < 10880)  { tile -= 8832; int l = tile / 256;  tile -= l * 256;
                              src = Wo + (size_t)l * DEC * DEC;
                              dst = wh + WT_O + (size_t)l * DEC * DEC; K = DEC; N = DEC; }
    else if (tile < 19072)  { tile -= 10880; int l = tile / 1024; tile -= l * 1024;
                              src = W1 + (size_t)l * DEC * FFN;
                              dst = wh + WT_W1 + (size_t)l * DEC * FFN; K = DEC; N = FFN; }
    else if (tile < 27264)  { tile -= 19072; int l = tile / 1024; tile -= l * 1024;
                              src = W2 + (size_t)l * FFN * DEC;
                              dst = wh + WT_W2 + (size_t)l * FFN * DEC; K = FFN; N = DEC; }
    else                    { tile -= 27264; src = Wr; dst = wh + WT_R; K = DEC; N = OUTD; }
    int ntx = N / 32;
    int kb = (tile / ntx) * 32, nb = (tile % ntx) * 32;
    #pragma unroll
    for (int i = 0; i < 4; i++)
        t[threadIdx.y + 8 * i][threadIdx.x] =
            src[(size_t)(kb + threadIdx.y + 8 * i) * N + nb + threadIdx.x];
    __syncthreads();
    #pragma unroll
    for (int i = 0; i < 4; i++)
        dst[(size_t)(nb + threadIdx.y + 8 * i) * K + kb + threadIdx.x] =
            __float2half_rn(t[threadIdx.x][threadIdx.y + 8 * i]);
}

// ---------------- mask scan ----------------
__global__ void scan_kernel(const int* __restrict__ mask) {
    int b = threadIdx.x;
    if (b >= B_) return;
    int cnt = 0;
    for (int n = 0; n < NPATCH; n++) {
        int m = mask[b * NPATCH + n];
        if (m == 0) {
            if (cnt < V_) g_visidx[b * V_ + cnt] = n;
            g_src[b * NPATCH + n] = (cnt < V_) ? cnt : (V_ - 1);
            cnt++;
        } else {
            g_src[b * NPATCH + n] = -1;
        }
    }
    for (int c = cnt; c < V_; c++) g_visidx[b * V_ + c] = 0;
}

// ---------------- patchify -> fp16 ----------------
__global__ void patchify_kernel(const float* __restrict__ x) {
    int r  = blockIdx.x;
    int b  = r / V_;
    int n  = g_visidx[r];
    int hp = n / (IMG / PSZ);
    int wp = n % (IMG / PSZ);
    for (int f = threadIdx.x; f < OUTD; f += blockDim.x) {
        int c  = f >> 8;
        int ph = (f >> 4) & 15;
        int pw = f & 15;
        float v = x[((b * CIN + c) * IMG + hp * PSZ + ph) * IMG + wp * PSZ + pw];
        g_patchh[(size_t)r * OUTD + f] = __float2half_rn(v);
    }
}

// ---------------- assemble ----------------
__global__ void assemble_kernel(const float* __restrict__ mask_token,
                                const float* __restrict__ pos_embed) {
    int row = blockIdx.x;
    int b = row / NPATCH;
    int n = row % NPATCH;
    int s = g_src[row];
    const float4* src = (s >= 0)
        ? (const float4*)&g_dec[(b * V_ + s) * DEC]
        : (const float4*)mask_token;
    const float4* pos = (const float4*)&pos_embed[n * DEC];
    int t = threadIdx.x;
    float4 a = src[t], p = pos[t];
    float4 v = make_float4(a.x + p.x, a.y + p.y, a.z + p.z, a.w + p.w);
    ((float4*)&g_h[(size_t)row * DEC])[t] = v;
    __half2* hh = (__half2*)&g_hh[(size_t)row * DEC];
    hh[t * 2 + 0] = __floats2half2_rn(v.x, v.y);
    hh[t * 2 + 1] = __floats2half2_rn(v.z, v.w);
}

// ---------------- fp16 tensor-core GEMM: BK=64, hoisted addressing ----
#define BM 128
#define BN 128
#define BK 64
#define STRH 72                          // halfs per smem row (64 + pad 8) = 144 B
#define TILEH (128 * STRH)               // 9216 halfs per tile
#define STAGEH (2 * TILEH)               // A + B
#define GEMM_SMEM (2 * STAGEH * 2)       // 73728 B
#define FLAG_GELU 1

__global__ __launch_bounds__(512, 2) void gemm_tc_kernel(
    const __half* __restrict__ A, const __half* __restrict__ Wt,
    const float* __restrict__ bias, const float* __restrict__ resid,
    float* __restrict__ C, __half* __restrict__ Ch,
    int M, int N, int K, int flags)
{
    extern __shared__ __half sm[];

    const int t = threadIdx.x;
    const int bn = blockIdx.x * BN;
    const int bm = blockIdx.y * BM;
    const int warp = t >> 5, lane = t & 31;
    const int wm = warp >> 2, wn = warp & 3;     // 4 x 4 warps, warp tile 32x32
    const int lq = lane >> 2, lr = lane & 3;
    const int g  = lane >> 3;                    // ldmatrix group 0..3
    const int gr = lane & 7;

    // ---- hoisted per-thread load descriptors (loop-invariant) ----
    const __half* srcs[4];
    uint32_t dsts[4];
    int oks[4];
    #pragma unroll
    for (int i = 0; i < 4; i++) {
        int idx  = t + (i << 9);             // 0..2047
        int part = idx >> 10;                // 0 = A, 1 = B
        int sub  = idx & 1023;
        int row  = sub >> 3;                 // 0..127
        int c8   = sub & 7;                  // 0..7
        if (part == 0) {
            int gr_ = bm + row;
            oks[i] = (gr_ < M) ? 16 : 0;
            if (gr_ >= M) gr_ = M - 1;
            srcs[i] = A + (size_t)gr_ * K + c8 * 8;
        } else {
            oks[i] = 16;
            srcs[i] = Wt + (size_t)(bn + row) * K + c8 * 8;
        }
        dsts[i] = (uint32_t)__cvta_generic_to_shared(sm + part * TILEH + row * STRH + c8 * 8);
    }
    const uint32_t stage_b = STAGEH * 2;     // bytes per stage

    float acc[2][4][4] = {};

    const int nch = K / BK;
    // stage 0 load
    #pragma unroll
    for (int i = 0; i < 4; i++) cp_async16u(dsts[i], srcs[i], oks[i]);
    asm volatile("cp.async.commit_group;\n");

    // hoisted ldmatrix bases (bytes)
    const int a_off = (wm * 32 + (g & 1) * 8 + gr) * STRH + (g >> 1) * 8;
    const int b_off = (wn * 32 + g * 8 + gr) * STRH;
    uint32_t a_base0 = (uint32_t)__cvta_generic_to_shared(sm + a_off);
    uint32_t b_base0 = (uint32_t)__cvta_generic_to_shared(sm + TILEH + b_off);

    for (int c = 0; c < nch; c++) {
        int s = c & 1;
        if (c + 1 < nch) {
            int k0 = (c + 1) * BK;
            uint32_t soff = (s ^ 1) * stage_b;
            #pragma unroll
            for (int i = 0; i < 4; i++)
                cp_async16u(dsts[i] + soff, srcs[i] + k0, oks[i]);
            asm volatile("cp.async.commit_group;\n");
            asm volatile("cp.async.wait_group 1;\n");
        } else {
            asm volatile("cp.async.wait_group 0;\n");
        }
        __syncthreads();

        uint32_t a_base = a_base0 + s * stage_b;
        uint32_t b_base = b_base0 + s * stage_b;

        #pragma unroll
        for (int ks = 0; ks < 4; ks++) {          // four k16 steps per BK=64 chunk
            const int kh = ks * 16;
            uint32_t af[2][4];
            uint32_t b0[4], b1[4];
            #pragma unroll
            for (int mi = 0; mi < 2; mi++)
                ldsm4(af[mi], a_base + (mi * 16 * STRH + kh) * 2);
            ldsm4(b0, b_base + (kh + 0) * 2);
            ldsm4(b1, b_base + (kh + 8) * 2);
            #pragma unroll
            for (int mi = 0; mi < 2; mi++)
                #pragma unroll
                for (int ni = 0; ni < 4; ni++) {
                    uint32_t bf[2] = { b0[ni], b1[ni] };
                    mma_f16(acc[mi][ni], af[mi], bf);
                }
        }
        __syncthreads();
    }

    const bool dogelu = (flags & FLAG_GELU) != 0;

    #pragma unroll
    for (int mi = 0; mi < 2; mi++) {
        int r0 = bm + wm * 32 + mi * 16 + lq;
        #pragma unroll
        for (int ni = 0; ni < 4; ni++) {
            int col = bn + wn * 32 + ni * 8 + lr * 2;
            float bx = bias[col], by = bias[col + 1];
            float* a4 = acc[mi][ni];
            #pragma unroll
            for (int half = 0; half < 2; half++) {
                int r = r0 + half * 8;
                if (r >= M) continue;
                float vx = a4[half * 2 + 0] + bx;
                float vy = a4[half * 2 + 1] + by;
                if (resid) {
                    const float* rr = resid + (size_t)r * N + col;
                    vx += rr[0]; vy += rr[1];
                }
                if (dogelu) { vx = gelu_exact(vx); vy = gelu_exact(vy); }
                if (C)
                    *(float2*)(C + (size_t)r * N + col) = make_float2(vx, vy);
                if (Ch)
                    *(__half2*)(Ch + (size_t)r * N + col) = __floats2half2_rn(vx, vy);
            }
        }
    }
}

// ---------------- layernorm: fp32 out + fp16 out ----------------
__global__ __launch_bounds__(128) void ln_kernel(
    const float* __restrict__ in, float* __restrict__ out, __half* __restrict__ outh,
    const float* __restrict__ gamma, const float* __restrict__ beta)
{
    __shared__ float red[8];
    int row = blockIdx.x;
    int t = threadIdx.x;
    float4 v = ((const float4*)(in + (size_t)row * DEC))[t];
    float s  = v.x + v.y + v.z + v.w;
    float sq = v.x * v.x + v.y * v.y + v.z * v.z + v.w * v.w;
    #pragma unroll
    for (int off = 16; off > 0; off >>= 1) {
        s  += __shfl_xor_sync(0xffffffff, s,  off);
        sq += __shfl_xor_sync(0xffffffff, sq, off);
    }
    int w = t >> 5;
    if ((t & 31) == 0) { red[w] = s; red[4 + w] = sq; }
    __syncthreads();
    s  = red[0] + red[1] + red[2] + red[3];
    sq = red[4] + red[5] + red[6] + red[7];
    float mu = s * (1.0f / DEC);
    float var = sq * (1.0f / DEC) - mu * mu;
    float rstd = rsqrtf(var + 1e-5f);
    float4 g = ((const float4*)gamma)[t];
    float4 b = ((const float4*)beta)[t];
    float4 o;
    o.x = (v.x - mu) * rstd * g.x + b.x;
    o.y = (v.y - mu) * rstd * g.y + b.y;
    o.z = (v.z - mu) * rstd * g.z + b.z;
    o.w = (v.w - mu) * rstd * g.w + b.w;
    ((float4*)(out + (size_t)row * DEC))[t] = o;
    __half2* hh = (__half2*)(outh + (size_t)row * DEC);
    hh[t * 2 + 0] = __floats2half2_rn(o.x, o.y);
    hh[t * 2 + 1] = __floats2half2_rn(o.z, o.w);
}

// ---------------- attention (fp16 qkv input; 2 query-blocks per (b,h)) ----------------
#define KSTRIDE 33
#define SM_K 0
#define SM_V (NPATCH * KSTRIDE)
#define SM_P (SM_V + NPATCH * HD)
#define ATTN_SMEM ((SM_P + 8 * NPATCH) * 4)

__global__ __launch_bounds__(256) void attn_kernel() {
    extern __shared__ float smf[];
    float* Ksm = smf + SM_K;
    float* Vsm = smf + SM_V;
    float* Psm = smf + SM_P;

    int bh = blockIdx.x >> 1;
    int qhalf = blockIdx.x & 1;
    int b = bh >> 4;
    int h = bh & 15;
    const __half* qkv = g_qkvh + (size_t)b * (NPATCH * 3 * DEC);
    int tid = threadIdx.x;

    for (int idx = tid; idx < NPATCH * HD; idx += 256) {
        int j = idx >> 5, d = idx & 31;
        Ksm[j * KSTRIDE + d] = __half2float(qkv[j * (3 * DEC) + DEC     + h * HD + d]);
        Vsm[j * HD      + d] = __half2float(qkv[j * (3 * DEC) + 2 * DEC + h * HD + d]);
    }
    __syncthreads();

    int warp = tid >> 5, lane = tid & 31;
    const float scale = 0.17677669529663687f;
    const int qstart = qhalf * 98;
    const int qend = qstart + 98;

    for (int i = qstart + warp; i < qend; i += 8) {
        const __half* q = qkv + i * (3 * DEC) + h * HD;
        float qr[HD];
        #pragma unroll
        for (int kk = 0; kk < HD; kk++) qr[kk] = __half2float(q[kk]);

        float s[7];
        float mx = -1e30f;
        #pragma unroll
        for (int jj = 0; jj < 7; jj++) {
            int j = jj * 32 + lane;
            float acc = -1e30f;
            if (j < NPATCH) {
                acc = 0.f;
                #pragma unroll
                for (int kk = 0; kk < HD; kk++) acc += qr[kk] * Ksm[j * KSTRIDE + kk];
                acc *= scale;
            }
            s[jj] = acc;
            mx = fmaxf(mx, acc);
        }
        #pragma unroll
        for (int off = 16; off > 0; off >>= 1)
            mx = fmaxf(mx, __shfl_xor_sync(0xffffffff, mx, off));

        float sum = 0.f;
        #pragma unroll
        for (int jj = 0; jj < 7; jj++) {
            int j = jj * 32 + lane;
            float p = (j < NPATCH) ? __expf(s[jj] - mx) : 0.f;
            if (j < NPATCH) Psm[warp * NPATCH + j] = p;
            sum += p;
        }
        #pragma unroll
        for (int off = 16; off > 0; off >>= 1)
            sum += __shfl_xor_sync(0xffffffff, sum, off);
        float inv = 1.0f / sum;
        __syncwarp();

        const float* pp = Psm + warp * NPATCH;
        float a0 = 0.f, a1 = 0.f, a2 = 0.f, a3 = 0.f;
        for (int j = 0; j < NPATCH; j += 4) {
            a0 += pp[j]     * Vsm[j * HD + lane];
            a1 += pp[j + 1] * Vsm[(j + 1) * HD + lane];
            a2 += pp[j + 2] * Vsm[(j + 2) * HD + lane];
            a3 += pp[j + 3] * Vsm[(j + 3) * HD + lane];
        }
        float acc = (a0 + a1) + (a2 + a3);
        g_attnh[((size_t)b * NPATCH + i) * DEC + h * HD + lane] = __float2half_rn(acc * inv);
        __syncwarp();
    }
}

// ---------------- host launchers ----------------
static inline void launch_gemm(const __half* A, const __half* Wt, const float* bias,
                               const float* resid, float* C, __half* Ch,
                               int M, int N, int K, int flags) {
    dim3 grid(N / BN, (M + BM - 1) / BM);
    gemm_tc_kernel<<<grid, 512, GEMM_SMEM>>>(A, Wt, bias, resid, C, Ch, M, N, K, flags);
}

extern "C" void kernel_launch(void* const* d_in, const int* in_sizes, int n_in,
                              void* d_out, int out_size) {
    const float* x          = (const float*)d_in[0];
    const int*   mask       = (const int*)  d_in[1];
    const float* Wp         = (const float*)d_in[3];
    const float* bp         = (const float*)d_in[4];
    const float* We2d       = (const float*)d_in[5];
    const float* be2d       = (const float*)d_in[6];
    const float* mask_token = (const float*)d_in[7];
    const float* pos_embed  = (const float*)d_in[8];
    const float* Wqkv       = (const float*)d_in[9];
    const float* bqkv       = (const float*)d_in[10];
    const float* Wo         = (const float*)d_in[11];
    const float* bo         = (const float*)d_in[12];
    const float* ln1g       = (const float*)d_in[13];
    const float* ln1b       = (const float*)d_in[14];
    const float* W1         = (const float*)d_in[15];
    const float* b1         = (const float*)d_in[16];
    const float* W2         = (const float*)d_in[17];
    const float* b2         = (const float*)d_in[18];
    const float* ln2g       = (const float*)d_in[19];
    const float* ln2b       = (const float*)d_in[20];
    const float* Wr         = (const float*)d_in[21];
    const float* br         = (const float*)d_in[22];

    float* out = (float*)d_out;
    float* rec = out;
    float* enc = out + (size_t)ROWS_N * OUTD;

    __half *p_patchh, *p_ench, *p_hh, *p_attnh, *p_qkvh, *p_ffnh, *p_wh;
    float  *p_dec, *p_h, *p_tmp;
    cudaGetSymbolAddress((void**)&p_patchh, g_patchh);
    cudaGetSymbolAddress((void**)&p_ench,   g_ench);
    cudaGetSymbolAddress((void**)&p_dec,    g_dec);
    cudaGetSymbolAddress((void**)&p_h,      g_h);
    cudaGetSymbolAddress((void**)&p_hh,     g_hh);
    cudaGetSymbolAddress((void**)&p_tmp,    g_tmp);
    cudaGetSymbolAddress((void**)&p_attnh,  g_attnh);
    cudaGetSymbolAddress((void**)&p_qkvh,   g_qkvh);
    cudaGetSymbolAddress((void**)&p_ffnh,   g_ffnh);
    cudaGetSymbolAddress((void**)&p_wh,     g_wh);

    cudaFuncSetAttribute(attn_kernel, cudaFuncAttributeMaxDynamicSharedMemorySize, ATTN_SMEM);
    cudaFuncSetAttribute(gemm_tc_kernel, cudaFuncAttributeMaxDynamicSharedMemorySize, GEMM_SMEM);

    fused_tr<<<28800, dim3(32, 8)>>>(Wp, We2d, Wqkv, Wo, W1, W2, Wr, p_wh);
    scan_kernel<<<1, 64>>>(mask);
    patchify_kernel<<<ROWS_V, 256>>>(x);

    launch_gemm(p_patchh, p_wh + WT_WP, bp, nullptr, enc, p_ench, ROWS_V, ENC, OUTD, 0);
    launch_gemm(p_ench, p_wh + WT_E2D, be2d, nullptr, p_dec, nullptr, ROWS_V, DEC, ENC, 0);
    assemble_kernel<<<ROWS_N, 128>>>(mask_token, pos_embed);

    for (int l = 0; l < NL; l++) {
        const __half* wh_qkv = p_wh + WT_QKV + (size_t)l * 3 * DEC * DEC;
        const __half* wh_o   = p_wh + WT_O   + (size_t)l * DEC * DEC;
        const __half* wh_1   = p_wh + WT_W1  + (size_t)l * DEC * FFN;
        const __half* wh_2   = p_wh + WT_W2  + (size_t)l * FFN * DEC;
        const float* bq  = bqkv + (size_t)l * 3 * DEC;
        const float* bol = bo   + (size_t)l * DEC;
        const float* b1l = b1   + (size_t)l * FFN;
        const float* b2l = b2   + (size_t)l * DEC;

        launch_gemm(p_hh, wh_qkv, bq, nullptr, nullptr, p_qkvh, ROWS_N, 3 * DEC, DEC, 0);
        attn_kernel<<<B_ * NH * 2, 256, ATTN_SMEM>>>();
        launch_gemm(p_attnh, wh_o, bol, p_h, p_tmp, nullptr, ROWS_N, DEC, DEC, 0);
        ln_kernel<<<ROWS_N, 128>>>(p_tmp, p_h, p_hh, ln1g + l * DEC, ln1b + l * DEC);
        launch_gemm(p_hh, wh_1, b1l, nullptr, nullptr, p_ffnh, ROWS_N, FFN, DEC, FLAG_GELU);
        launch_gemm(p_ffnh, wh_2, b2l, p_h, p_tmp, nullptr, ROWS_N, DEC, FFN, 0);
        ln_kernel<<<ROWS_N, 128>>>(p_tmp, p_h, p_hh, ln2g + l * DEC, ln2b + l * DEC);
    }

    launch_gemm(p_hh, p_wh + WT_R, br, nullptr, rec, nullptr, ROWS_N, OUTD, DEC, 0);
}

// round 16
// speedup vs baseline: 1.2740x; 1.1967x over previous
#include <cuda_runtime.h>
#include <cuda_fp16.h>
#include <cstdint>
#include <math.h>

// ---------------- problem constants ----------------
#define B_      64
#define V_      49
#define NPATCH  196
#define CIN     12
#define PSZ     16
#define IMG     224
#define ENC     768
#define DEC     512
#define NL      8
#define NH      16
#define HD      32
#define FFN     2048
#define OUTD    3072
#define ROWS_V  (B_ * V_)       // 3136
#define ROWS_N  (B_ * NPATCH)   // 12544

// ---------------- scratch ----------------
__device__ __half g_patchh[ROWS_V * OUTD];
__device__ __half g_ench  [ROWS_V * ENC];
__device__ float  g_dec   [ROWS_V * DEC];
__device__ float  g_h     [ROWS_N * DEC];
__device__ __half g_hh    [ROWS_N * DEC];
__device__ float  g_tmp   [ROWS_N * DEC];
__device__ __half g_attnh [ROWS_N * DEC];
__device__ __half g_qkvh  [ROWS_N * 3 * DEC];
__device__ __half g_ffnh  [ROWS_N * FFN];
__device__ __half g_wh    [29491200];        // fp16 weights, TRANSPOSED to [N,K]
__device__ int    g_visidx[B_ * V_];
__device__ int    g_src   [B_ * NPATCH];

// weight-scratch offsets (halfs)
#define WT_WP   0
#define WT_E2D  2359296
#define WT_QKV  2752512
#define WT_O    9043968
#define WT_W1   11141120
#define WT_W2   19529728
#define WT_R    27918336

// ---------------- helpers ----------------
__device__ __forceinline__ float gelu_exact(float v) {
    return 0.5f * v * (1.0f + erff(v * 0.7071067811865476f));
}
__device__ __forceinline__ void cp_async16u(uint32_t saddr, const void* gsrc, int sz) {
    asm volatile("cp.async.cg.shared.global [%0], [%1], 16, %2;\n"
                 :: "r"(saddr), "l"(gsrc), "r"(sz));
}
__device__ __forceinline__ void mma_f16(float* c, const uint32_t* a, const uint32_t* b) {
    asm volatile(
        "mma.sync.aligned.m16n8k16.row.col.f32.f16.f16.f32 "
        "{%0,%1,%2,%3}, {%4,%5,%6,%7}, {%8,%9}, {%0,%1,%2,%3};"
        : "+f"(c[0]), "+f"(c[1]), "+f"(c[2]), "+f"(c[3])
        : "r"(a[0]), "r"(a[1]), "r"(a[2]), "r"(a[3]), "r"(b[0]), "r"(b[1]));
}
__device__ __forceinline__ void ldsm4(uint32_t* r, uint32_t saddr) {
    asm volatile("ldmatrix.sync.aligned.m8n8.x4.shared.b16 {%0,%1,%2,%3}, [%4];"
                 : "=r"(r[0]), "=r"(r[1]), "=r"(r[2]), "=r"(r[3]) : "r"(saddr));
}

// ---------------- fused weight prep: all transposes in one kernel ----------------
__global__ void fused_tr(const float* __restrict__ Wp, const float* __restrict__ We2d,
                         const float* __restrict__ Wqkv, const float* __restrict__ Wo,
                         const float* __restrict__ W1, const float* __restrict__ W2,
                         const float* __restrict__ Wr, __half* __restrict__ wh) {
    __shared__ float t[32][33];
    int tile = blockIdx.x;
    const float* src; __half* dst; int K, N;
    if (tile < 2304)        { src = Wp;   dst = wh + WT_WP;  K = OUTD; N = ENC; }
    else if (tile < 2688)   { tile -= 2304; src = We2d; dst = wh + WT_E2D; K = ENC; N = DEC; }
    else if (tile < 8832)   { tile -= 2688; int l = tile / 768;  tile -= l * 768;
                              src = Wqkv + (size_t)l * DEC * 3 * DEC;
                              dst = wh + WT_QKV + (size_t)l * 3 * DEC * DEC; K = DEC; N = 3 * DEC; }
    else if (tile < 10880)  { tile -= 8832; int l = tile / 256;  tile -= l * 256;
                              src = Wo + (size_t)l * DEC * DEC;
                              dst = wh + WT_O + (size_t)l * DEC * DEC; K = DEC; N = DEC; }
    else if (tile < 19072)  { tile -= 10880; int l = tile / 1024; tile -= l * 1024;
                              src = W1 + (size_t)l * DEC * FFN;
                              dst = wh + WT_W1 + (size_t)l * DEC * FFN; K = DEC; N = FFN; }
    else if (tile < 27264)  { tile -= 19072; int l = tile / 1024; tile -= l * 1024;
                              src = W2 + (size_t)l * FFN * DEC;
                              dst = wh + WT_W2 + (size_t)l * FFN * DEC; K = FFN; N = DEC; }
    else                    { tile -= 27264; src = Wr; dst = wh + WT_R; K = DEC; N = OUTD; }
    int ntx = N / 32;
    int kb = (tile / ntx) * 32, nb = (tile % ntx) * 32;
    #pragma unroll
    for (int i = 0; i < 4; i++)
        t[threadIdx.y + 8 * i][threadIdx.x] =
            src[(size_t)(kb + threadIdx.y + 8 * i) * N + nb + threadIdx.x];
    __syncthreads();
    #pragma unroll
    for (int i = 0; i < 4; i++)
        dst[(size_t)(nb + threadIdx.y + 8 * i) * K + kb + threadIdx.x] =
            __float2half_rn(t[threadIdx.x][threadIdx.y + 8 * i]);
}

// ---------------- mask scan ----------------
__global__ void scan_kernel(const int* __restrict__ mask) {
    int b = threadIdx.x;
    if (b >= B_) return;
    int cnt = 0;
    for (int n = 0; n < NPATCH; n++) {
        int m = mask[b * NPATCH + n];
        if (m == 0) {
            if (cnt < V_) g_visidx[b * V_ + cnt] = n;
            g_src[b * NPATCH + n] = (cnt < V_) ? cnt : (V_ - 1);
            cnt++;
        } else {
            g_src[b * NPATCH + n] = -1;
        }
    }
    for (int c = cnt; c < V_; c++) g_visidx[b * V_ + c] = 0;
}

// ---------------- patchify -> fp16 ----------------
__global__ void patchify_kernel(const float* __restrict__ x) {
    int r  = blockIdx.x;
    int b  = r / V_;
    int n  = g_visidx[r];
    int hp = n / (IMG / PSZ);
    int wp = n % (IMG / PSZ);
    for (int f = threadIdx.x; f < OUTD; f += blockDim.x) {
        int c  = f >> 8;
        int ph = (f >> 4) & 15;
        int pw = f & 15;
        float v = x[((b * CIN + c) * IMG + hp * PSZ + ph) * IMG + wp * PSZ + pw];
        g_patchh[(size_t)r * OUTD + f] = __float2half_rn(v);
    }
}

// ---------------- assemble ----------------
__global__ void assemble_kernel(const float* __restrict__ mask_token,
                                const float* __restrict__ pos_embed) {
    int row = blockIdx.x;
    int b = row / NPATCH;
    int n = row % NPATCH;
    int s = g_src[row];
    const float4* src = (s >= 0)
        ? (const float4*)&g_dec[(b * V_ + s) * DEC]
        : (const float4*)mask_token;
    const float4* pos = (const float4*)&pos_embed[n * DEC];
    int t = threadIdx.x;
    float4 a = src[t], p = pos[t];
    float4 v = make_float4(a.x + p.x, a.y + p.y, a.z + p.z, a.w + p.w);
    ((float4*)&g_h[(size_t)row * DEC])[t] = v;
    __half2* hh = (__half2*)&g_hh[(size_t)row * DEC];
    hh[t * 2 + 0] = __floats2half2_rn(v.x, v.y);
    hh[t * 2 + 1] = __floats2half2_rn(v.z, v.w);
}

// ---------------- fp16 tensor-core GEMM: BK=64, hoisted addressing ----
#define BM 128
#define BN 128
#define BK 64
#define STRH 72                          // halfs per smem row (64 + pad 8) = 144 B
#define TILEH (128 * STRH)               // 9216 halfs per tile
#define STAGEH (2 * TILEH)               // A + B
#define GEMM_SMEM (2 * STAGEH * 2)       // 73728 B
#define FLAG_GELU 1

__global__ __launch_bounds__(512, 2) void gemm_tc_kernel(
    const __half* __restrict__ A, const __half* __restrict__ Wt,
    const float* __restrict__ bias, const float* __restrict__ resid,
    float* __restrict__ C, __half* __restrict__ Ch,
    int M, int N, int K, int flags)
{
    extern __shared__ __half sm[];

    const int t = threadIdx.x;
    const int bn = blockIdx.x * BN;
    const int bm = blockIdx.y * BM;
    const int warp = t >> 5, lane = t & 31;
    const int wm = warp >> 2, wn = warp & 3;     // 4 x 4 warps, warp tile 32x32
    const int lq = lane >> 2, lr = lane & 3;
    const int g  = lane >> 3;
    const int gr = lane & 7;

    // hoisted per-thread load descriptors
    const __half* srcs[4];
    uint32_t dsts[4];
    int oks[4];
    #pragma unroll
    for (int i = 0; i < 4; i++) {
        int idx  = t + (i << 9);
        int part = idx >> 10;
        int sub  = idx & 1023;
        int row  = sub >> 3;
        int c8   = sub & 7;
        if (part == 0) {
            int gr_ = bm + row;
            oks[i] = (gr_ < M) ? 16 : 0;
            if (gr_ >= M) gr_ = M - 1;
            srcs[i] = A + (size_t)gr_ * K + c8 * 8;
        } else {
            oks[i] = 16;
            srcs[i] = Wt + (size_t)(bn + row) * K + c8 * 8;
        }
        dsts[i] = (uint32_t)__cvta_generic_to_shared(sm + part * TILEH + row * STRH + c8 * 8);
    }
    const uint32_t stage_b = STAGEH * 2;

    float acc[2][4][4] = {};

    const int nch = K / BK;
    #pragma unroll
    for (int i = 0; i < 4; i++) cp_async16u(dsts[i], srcs[i], oks[i]);
    asm volatile("cp.async.commit_group;\n");

    const int a_off = (wm * 32 + (g & 1) * 8 + gr) * STRH + (g >> 1) * 8;
    const int b_off = (wn * 32 + g * 8 + gr) * STRH;
    uint32_t a_base0 = (uint32_t)__cvta_generic_to_shared(sm + a_off);
    uint32_t b_base0 = (uint32_t)__cvta_generic_to_shared(sm + TILEH + b_off);

    for (int c = 0; c < nch; c++) {
        int s = c & 1;
        if (c + 1 < nch) {
            int k0 = (c + 1) * BK;
            uint32_t soff = (s ^ 1) * stage_b;
            #pragma unroll
            for (int i = 0; i < 4; i++)
                cp_async16u(dsts[i] + soff, srcs[i] + k0, oks[i]);
            asm volatile("cp.async.commit_group;\n");
            asm volatile("cp.async.wait_group 1;\n");
        } else {
            asm volatile("cp.async.wait_group 0;\n");
        }
        __syncthreads();

        uint32_t a_base = a_base0 + s * stage_b;
        uint32_t b_base = b_base0 + s * stage_b;

        #pragma unroll
        for (int ks = 0; ks < 4; ks++) {
            const int kh = ks * 16;
            uint32_t af[2][4];
            uint32_t b0[4], b1[4];
            #pragma unroll
            for (int mi = 0; mi < 2; mi++)
                ldsm4(af[mi], a_base + (mi * 16 * STRH + kh) * 2);
            ldsm4(b0, b_base + (kh + 0) * 2);
            ldsm4(b1, b_base + (kh + 8) * 2);
            #pragma unroll
            for (int mi = 0; mi < 2; mi++)
                #pragma unroll
                for (int ni = 0; ni < 4; ni++) {
                    uint32_t bf[2] = { b0[ni], b1[ni] };
                    mma_f16(acc[mi][ni], af[mi], bf);
                }
        }
        __syncthreads();
    }

    const bool dogelu = (flags & FLAG_GELU) != 0;

    #pragma unroll
    for (int mi = 0; mi < 2; mi++) {
        int r0 = bm + wm * 32 + mi * 16 + lq;
        #pragma unroll
        for (int ni = 0; ni < 4; ni++) {
            int col = bn + wn * 32 + ni * 8 + lr * 2;
            float bx = bias[col], by = bias[col + 1];
            float* a4 = acc[mi][ni];
            #pragma unroll
            for (int half = 0; half < 2; half++) {
                int r = r0 + half * 8;
                if (r >= M) continue;
                float vx = a4[half * 2 + 0] + bx;
                float vy = a4[half * 2 + 1] + by;
                if (resid) {
                    const float* rr = resid + (size_t)r * N + col;
                    vx += rr[0]; vy += rr[1];
                }
                if (dogelu) { vx = gelu_exact(vx); vy = gelu_exact(vy); }
                if (C)
                    *(float2*)(C + (size_t)r * N + col) = make_float2(vx, vy);
                if (Ch)
                    *(__half2*)(Ch + (size_t)r * N + col) = __floats2half2_rn(vx, vy);
            }
        }
    }
}

// ---------------- layernorm: fp32 out + fp16 out ----------------
__global__ __launch_bounds__(128) void ln_kernel(
    const float* __restrict__ in, float* __restrict__ out, __half* __restrict__ outh,
    const float* __restrict__ gamma, const float* __restrict__ beta)
{
    __shared__ float red[8];
    int row = blockIdx.x;
    int t = threadIdx.x;
    float4 v = ((const float4*)(in + (size_t)row * DEC))[t];
    float s  = v.x + v.y + v.z + v.w;
    float sq = v.x * v.x + v.y * v.y + v.z * v.z + v.w * v.w;
    #pragma unroll
    for (int off = 16; off > 0; off >>= 1) {
        s  += __shfl_xor_sync(0xffffffff, s,  off);
        sq += __shfl_xor_sync(0xffffffff, sq, off);
    }
    int w = t >> 5;
    if ((t & 31) == 0) { red[w] = s; red[4 + w] = sq; }
    __syncthreads();
    s  = red[0] + red[1] + red[2] + red[3];
    sq = red[4] + red[5] + red[6] + red[7];
    float mu = s * (1.0f / DEC);
    float var = sq * (1.0f / DEC) - mu * mu;
    float rstd = rsqrtf(var + 1e-5f);
    float4 g = ((const float4*)gamma)[t];
    float4 b = ((const float4*)beta)[t];
    float4 o;
    o.x = (v.x - mu) * rstd * g.x + b.x;
    o.y = (v.y - mu) * rstd * g.y + b.y;
    o.z = (v.z - mu) * rstd * g.z + b.z;
    o.w = (v.w - mu) * rstd * g.w + b.w;
    ((float4*)(out + (size_t)row * DEC))[t] = o;
    __half2* hh = (__half2*)(outh + (size_t)row * DEC);
    hh[t * 2 + 0] = __floats2half2_rn(o.x, o.y);
    hh[t * 2 + 1] = __floats2half2_rn(o.z, o.w);
}

// ---------------- attention: 1 block per (b,h), 2 queries per warp ----------------
#define KSTRIDE 33
#define SM_K 0
#define SM_V (NPATCH * KSTRIDE)
#define SM_P (SM_V + NPATCH * HD)
#define ATTN_SMEM ((SM_P + 16 * NPATCH) * 4)   // 63504 B

__global__ __launch_bounds__(256) void attn_kernel() {
    extern __shared__ float smf[];
    float* Ksm = smf + SM_K;
    float* Vsm = smf + SM_V;
    float* Psm = smf + SM_P;

    int bh = blockIdx.x;
    int b = bh >> 4;
    int h = bh & 15;
    const __half* qkv = g_qkvh + (size_t)b * (NPATCH * 3 * DEC);
    int tid = threadIdx.x;

    for (int idx = tid; idx < NPATCH * HD; idx += 256) {
        int j = idx >> 5, d = idx & 31;
        Ksm[j * KSTRIDE + d] = __half2float(qkv[j * (3 * DEC) + DEC     + h * HD + d]);
        Vsm[j * HD      + d] = __half2float(qkv[j * (3 * DEC) + 2 * DEC + h * HD + d]);
    }
    __syncthreads();

    int warp = tid >> 5, lane = tid & 31;
    const float scale = 0.17677669529663687f;

    // 98 query pairs; each warp takes pairs warp, warp+8, ...
    for (int p = warp; p < NPATCH / 2; p += 8) {
        int q0 = 2 * p, q1 = 2 * p + 1;
        const __half* qp0 = qkv + q0 * (3 * DEC) + h * HD;
        const __half* qp1 = qkv + q1 * (3 * DEC) + h * HD;
        float qr0[HD], qr1[HD];
        #pragma unroll
        for (int kk = 0; kk < HD; kk++) {
            qr0[kk] = __half2float(qp0[kk]);
            qr1[kk] = __half2float(qp1[kk]);
        }

        float s0[7], s1[7];
        float mx0 = -1e30f, mx1 = -1e30f;
        #pragma unroll
        for (int jj = 0; jj < 7; jj++) {
            int j = jj * 32 + lane;
            float a0 = -1e30f, a1 = -1e30f;
            if (j < NPATCH) {
                a0 = 0.f; a1 = 0.f;
                const float* kr = Ksm + j * KSTRIDE;
                #pragma unroll
                for (int kk = 0; kk < HD; kk++) {
                    float kv = kr[kk];
                    a0 += qr0[kk] * kv;
                    a1 += qr1[kk] * kv;
                }
                a0 *= scale; a1 *= scale;
            }
            s0[jj] = a0; s1[jj] = a1;
            mx0 = fmaxf(mx0, a0); mx1 = fmaxf(mx1, a1);
        }
        #pragma unroll
        for (int off = 16; off > 0; off >>= 1) {
            mx0 = fmaxf(mx0, __shfl_xor_sync(0xffffffff, mx0, off));
            mx1 = fmaxf(mx1, __shfl_xor_sync(0xffffffff, mx1, off));
        }

        float sum0 = 0.f, sum1 = 0.f;
        float* pp0 = Psm + (2 * warp + 0) * NPATCH;
        float* pp1 = Psm + (2 * warp + 1) * NPATCH;
        #pragma unroll
        for (int jj = 0; jj < 7; jj++) {
            int j = jj * 32 + lane;
            float e0 = (j < NPATCH) ? __expf(s0[jj] - mx0) : 0.f;
            float e1 = (j < NPATCH) ? __expf(s1[jj] - mx1) : 0.f;
            if (j < NPATCH) { pp0[j] = e0; pp1[j] = e1; }
            sum0 += e0; sum1 += e1;
        }
        #pragma unroll
        for (int off = 16; off > 0; off >>= 1) {
            sum0 += __shfl_xor_sync(0xffffffff, sum0, off);
            sum1 += __shfl_xor_sync(0xffffffff, sum1, off);
        }
        float inv0 = 1.0f / sum0, inv1 = 1.0f / sum1;
        __syncwarp();

        float a00 = 0.f, a01 = 0.f, a10 = 0.f, a11 = 0.f;
        for (int j = 0; j < NPATCH; j += 2) {
            float v0 = Vsm[j * HD + lane];
            float v1 = Vsm[(j + 1) * HD + lane];
            a00 += pp0[j] * v0;     a10 += pp1[j] * v0;
            a01 += pp0[j + 1] * v1; a11 += pp1[j + 1] * v1;
        }
        float o0 = (a00 + a01) * inv0;
        float o1 = (a10 + a11) * inv1;
        g_attnh[((size_t)b * NPATCH + q0) * DEC + h * HD + lane] = __float2half_rn(o0);
        g_attnh[((size_t)b * NPATCH + q1) * DEC + h * HD + lane] = __float2half_rn(o1);
        __syncwarp();
    }
}

// ---------------- host launchers ----------------
static inline void launch_gemm(const __half* A, const __half* Wt, const float* bias,
                               const float* resid, float* C, __half* Ch,
                               int M, int N, int K, int flags) {
    dim3 grid(N / BN, (M + BM - 1) / BM);
    gemm_tc_kernel<<<grid, 512, GEMM_SMEM>>>(A, Wt, bias, resid, C, Ch, M, N, K, flags);
}

extern "C" void kernel_launch(void* const* d_in, const int* in_sizes, int n_in,
                              void* d_out, int out_size) {
    const float* x          = (const float*)d_in[0];
    const int*   mask       = (const int*)  d_in[1];
    const float* Wp         = (const float*)d_in[3];
    const float* bp         = (const float*)d_in[4];
    const float* We2d       = (const float*)d_in[5];
    const float* be2d       = (const float*)d_in[6];
    const float* mask_token = (const float*)d_in[7];
    const float* pos_embed  = (const float*)d_in[8];
    const float* Wqkv       = (const float*)d_in[9];
    const float* bqkv       = (const float*)d_in[10];
    const float* Wo         = (const float*)d_in[11];
    const float* bo         = (const float*)d_in[12];
    const float* ln1g       = (const float*)d_in[13];
    const float* ln1b       = (const float*)d_in[14];
    const float* W1         = (const float*)d_in[15];
    const float* b1         = (const float*)d_in[16];
    const float* W2         = (const float*)d_in[17];
    const float* b2         = (const float*)d_in[18];
    const float* ln2g       = (const float*)d_in[19];
    const float* ln2b       = (const float*)d_in[20];
    const float* Wr         = (const float*)d_in[21];
    const float* br         = (const float*)d_in[22];

    float* out = (float*)d_out;
    float* rec = out;
    float* enc = out + (size_t)ROWS_N * OUTD;

    __half *p_patchh, *p_ench, *p_hh, *p_attnh, *p_qkvh, *p_ffnh, *p_wh;
    float  *p_dec, *p_h, *p_tmp;
    cudaGetSymbolAddress((void**)&p_patchh, g_patchh);
    cudaGetSymbolAddress((void**)&p_ench,   g_ench);
    cudaGetSymbolAddress((void**)&p_dec,    g_dec);
    cudaGetSymbolAddress((void**)&p_h,      g_h);
    cudaGetSymbolAddress((void**)&p_hh,     g_hh);
    cudaGetSymbolAddress((void**)&p_tmp,    g_tmp);
    cudaGetSymbolAddress((void**)&p_attnh,  g_attnh);
    cudaGetSymbolAddress((void**)&p_qkvh,   g_qkvh);
    cudaGetSymbolAddress((void**)&p_ffnh,   g_ffnh);
    cudaGetSymbolAddress((void**)&p_wh,     g_wh);

    cudaFuncSetAttribute(attn_kernel, cudaFuncAttributeMaxDynamicSharedMemorySize, ATTN_SMEM);
    cudaFuncSetAttribute(gemm_tc_kernel, cudaFuncAttributeMaxDynamicSharedMemorySize, GEMM_SMEM);

    fused_tr<<<28800, dim3(32, 8)>>>(Wp, We2d, Wqkv, Wo, W1, W2, Wr, p_wh);
    scan_kernel<<<1, 64>>>(mask);
    patchify_kernel<<<ROWS_V, 256>>>(x);

    launch_gemm(p_patchh, p_wh + WT_WP, bp, nullptr, enc, p_ench, ROWS_V, ENC, OUTD, 0);
    launch_gemm(p_ench, p_wh + WT_E2D, be2d, nullptr, p_dec, nullptr, ROWS_V, DEC, ENC, 0);
    assemble_kernel<<<ROWS_N, 128>>>(mask_token, pos_embed);

    for (int l = 0; l < NL; l++) {
        const __half* wh_qkv = p_wh + WT_QKV + (size_t)l * 3 * DEC * DEC;
        const __half* wh_o   = p_wh + WT_O   + (size_t)l * DEC * DEC;
        const __half* wh_1   = p_wh + WT_W1  + (size_t)l * DEC * FFN;
        const __half* wh_2   = p_wh + WT_W2  + (size_t)l * FFN * DEC;
        const float* bq  = bqkv + (size_t)l * 3 * DEC;
        const float* bol = bo   + (size_t)l * DEC;
        const float* b1l = b1   + (size_t)l * FFN;
        const float* b2l = b2   + (size_t)l * DEC;

        launch_gemm(p_hh, wh_qkv, bq, nullptr, nullptr, p_qkvh, ROWS_N, 3 * DEC, DEC, 0);
        attn_kernel<<<B_ * NH, 256, ATTN_SMEM>>>();
        launch_gemm(p_attnh, wh_o, bol, p_h, p_tmp, nullptr, ROWS_N, DEC, DEC, 0);
        ln_kernel<<<ROWS_N, 128>>>(p_tmp, p_h, p_hh, ln1g + l * DEC, ln1b + l * DEC);
        launch_gemm(p_hh, wh_1, b1l, nullptr, nullptr, p_ffnh, ROWS_N, FFN, DEC, FLAG_GELU);
        launch_gemm(p_ffnh, wh_2, b2l, p_h, p_tmp, nullptr, ROWS_N, DEC, FFN, 0);
        ln_kernel<<<ROWS_N, 128>>>(p_tmp, p_h, p_hh, ln2g + l * DEC, ln2b + l * DEC);
    }

    launch_gemm(p_hh, p_wh + WT_R, br, nullptr, rec, nullptr, ROWS_N, OUTD, DEC, 0);
}